// round 1
// baseline (speedup 1.0000x reference)
#include <cuda_runtime.h>

// Tucker-factorized linear layer:
//   z[n,lmn] = sum_{def} f3[d,l] f4[e,m] f5[f,nn] x[n,d,e,f]
//   u[n,ijk] = sum_{lmn} core[ijk,lmn] z[n,lmn]
//   y[n,abc] = sum_{ijk} f0[a,i] f1[b,j] f2[c,k] u[n,ijk] + bias[abc]

#define NS 4096   // samples

__device__ float g_Z[NS * 512];
__device__ float g_U[NS * 512];

// ---------------- K1: in-side contraction (one CTA per sample) ----------------
__global__ __launch_bounds__(128) void k_in(const float* __restrict__ x,
                                            const float* __restrict__ f3,
                                            const float* __restrict__ f4,
                                            const float* __restrict__ f5) {
    __shared__ float xs[4096];        // x row [d][e][f]
    __shared__ float t1[8 * 16 * 16]; // [l][e][f]
    __shared__ float t2[8 * 8 * 16];  // [l][m][f]
    __shared__ float f3s[128], f4s[128], f5s[128];
    const int tid = threadIdx.x;
    const int n = blockIdx.x;

    f3s[tid] = f3[tid];
    f4s[tid] = f4[tid];
    f5s[tid] = f5[tid];

    const float4* xin = (const float4*)(x + (size_t)n * 4096);
    float4* xs4 = (float4*)xs;
#pragma unroll
    for (int i = 0; i < 8; i++) xs4[tid + i * 128] = xin[tid + i * 128];
    __syncthreads();

    // stage 1: t1[l,e,f] = sum_d f3[d,l] * x[d,e,f]
#pragma unroll
    for (int i = 0; i < 16; i++) {
        int idx = tid + i * 128;          // idx = l*256 + e*16 + f
        int l = idx >> 8, ef = idx & 255;
        float acc = 0.f;
#pragma unroll
        for (int d = 0; d < 16; d++) acc += f3s[d * 8 + l] * xs[d * 256 + ef];
        t1[idx] = acc;
    }
    __syncthreads();

    // stage 2: t2[l,m,f] = sum_e f4[e,m] * t1[l,e,f]
#pragma unroll
    for (int i = 0; i < 8; i++) {
        int idx = tid + i * 128;          // idx = l*128 + m*16 + f
        int f = idx & 15, m = (idx >> 4) & 7, l = idx >> 7;
        float acc = 0.f;
#pragma unroll
        for (int e = 0; e < 16; e++) acc += f4s[e * 8 + m] * t1[(l * 16 + e) * 16 + f];
        t2[idx] = acc;
    }
    __syncthreads();

    // stage 3: z[l,m,nn] = sum_f f5[f,nn] * t2[l,m,f]
    float* zo = g_Z + (size_t)n * 512;
#pragma unroll
    for (int i = 0; i < 4; i++) {
        int idx = tid + i * 128;          // idx = (l*8+m)*8 + nn
        int nn = idx & 7, lm = idx >> 3;
        float acc = 0.f;
#pragma unroll
        for (int f = 0; f < 16; f++) acc += f5s[f * 8 + nn] * t2[lm * 16 + f];
        zo[idx] = acc;
    }
}

// ---------------- K2: core GEMM  U[M=4096, N=512] = Z[M,K=512] * C[N,K]^T ----------------
// Tile 128x128xK16, 256 threads, 8x8 micro-tile with split-4 fragments.
__global__ __launch_bounds__(256) void k_core(const float* __restrict__ C) {
    __shared__ float As[16][128];  // As[k][m]
    __shared__ float Bs[16][128];  // Bs[k][o]
    const int tid = threadIdx.x;
    const int mBase = blockIdx.y * 128;
    const int nBase = blockIdx.x * 128;
    const int tx = tid & 15, ty = tid >> 4;

    float acc[8][8];
#pragma unroll
    for (int i = 0; i < 8; i++)
#pragma unroll
        for (int j = 0; j < 8; j++) acc[i][j] = 0.f;

    const int lm = tid >> 2;          // 0..63
    const int lk = (tid & 3) * 4;     // 0,4,8,12

    for (int k0 = 0; k0 < 512; k0 += 16) {
#pragma unroll
        for (int h = 0; h < 2; h++) {
            int m = lm + h * 64;
            float4 va = *(const float4*)&g_Z[(size_t)(mBase + m) * 512 + k0 + lk];
            As[lk + 0][m] = va.x; As[lk + 1][m] = va.y;
            As[lk + 2][m] = va.z; As[lk + 3][m] = va.w;
            float4 vb = *(const float4*)&C[(size_t)(nBase + m) * 512 + k0 + lk];
            Bs[lk + 0][m] = vb.x; Bs[lk + 1][m] = vb.y;
            Bs[lk + 2][m] = vb.z; Bs[lk + 3][m] = vb.w;
        }
        __syncthreads();
#pragma unroll
        for (int k = 0; k < 16; k++) {
            float a[8], b[8];
            *(float4*)&a[0] = *(const float4*)&As[k][ty * 4];
            *(float4*)&a[4] = *(const float4*)&As[k][64 + ty * 4];
            *(float4*)&b[0] = *(const float4*)&Bs[k][tx * 4];
            *(float4*)&b[4] = *(const float4*)&Bs[k][64 + tx * 4];
#pragma unroll
            for (int i = 0; i < 8; i++)
#pragma unroll
                for (int j = 0; j < 8; j++) acc[i][j] += a[i] * b[j];
        }
        __syncthreads();
    }

#pragma unroll
    for (int i = 0; i < 8; i++) {
        int m = mBase + ((i < 4) ? (ty * 4 + i) : (64 + ty * 4 + (i - 4)));
#pragma unroll
        for (int jh = 0; jh < 2; jh++) {
            float4 v;
            v.x = acc[i][jh * 4 + 0];
            v.y = acc[i][jh * 4 + 1];
            v.z = acc[i][jh * 4 + 2];
            v.w = acc[i][jh * 4 + 3];
            int o = nBase + (jh ? (64 + tx * 4) : (tx * 4));
            *(float4*)&g_U[(size_t)m * 512 + o] = v;
        }
    }
}

// ---------------- K3: out-side expansion (one CTA per sample) ----------------
__global__ __launch_bounds__(128) void k_out(const float* __restrict__ f0,
                                             const float* __restrict__ f1,
                                             const float* __restrict__ f2,
                                             const float* __restrict__ bias,
                                             float* __restrict__ y) {
    __shared__ float us[512];          // u[i][j][k]
    __shared__ float s1[16 * 8 * 8];   // [a][j][k]
    __shared__ float s2[16 * 16 * 8];  // [a][b][k]
    __shared__ float f0s[128], f1s[128], f2s[128];
    const int tid = threadIdx.x;
    const int n = blockIdx.x;

    f0s[tid] = f0[tid];
    f1s[tid] = f1[tid];
    f2s[tid] = f2[tid];

    const float4* uin = (const float4*)(g_U + (size_t)n * 512);
    ((float4*)us)[tid] = uin[tid];
    __syncthreads();

    // s1[a,j,k] = sum_i f0[a,i] * u[i,j,k]
#pragma unroll
    for (int t = 0; t < 8; t++) {
        int idx = tid + t * 128;        // idx = a*64 + j*8 + k
        int k = idx & 7, j = (idx >> 3) & 7, a = idx >> 6;
        float acc = 0.f;
#pragma unroll
        for (int i = 0; i < 8; i++) acc += f0s[a * 8 + i] * us[(i * 8 + j) * 8 + k];
        s1[idx] = acc;
    }
    __syncthreads();

    // s2[a,b,k] = sum_j f1[b,j] * s1[a,j,k]
#pragma unroll
    for (int t = 0; t < 16; t++) {
        int idx = tid + t * 128;        // idx = a*128 + b*8 + k
        int k = idx & 7, b = (idx >> 3) & 15, a = idx >> 7;
        float acc = 0.f;
#pragma unroll
        for (int j = 0; j < 8; j++) acc += f1s[b * 8 + j] * s1[a * 64 + j * 8 + k];
        s2[idx] = acc;
    }
    __syncthreads();

    // y[a,b,c] = sum_k f2[c,k] * s2[a,b,k] + bias
    float* yo = y + (size_t)n * 4096;
#pragma unroll
    for (int t = 0; t < 32; t++) {
        int idx = tid + t * 128;        // idx = (a*16+b)*16 + c
        int c = idx & 15, ab = idx >> 4;
        float acc = 0.f;
#pragma unroll
        for (int k = 0; k < 8; k++) acc += f2s[c * 8 + k] * s2[ab * 8 + k];
        yo[idx] = acc + bias[idx];
    }
}

extern "C" void kernel_launch(void* const* d_in, const int* in_sizes, int n_in,
                              void* d_out, int out_size) {
    const float* x    = (const float*)d_in[0];
    const float* core = (const float*)d_in[1];
    const float* f0   = (const float*)d_in[2];
    const float* f1   = (const float*)d_in[3];
    const float* f2   = (const float*)d_in[4];
    const float* f3   = (const float*)d_in[5];
    const float* f4   = (const float*)d_in[6];
    const float* f5   = (const float*)d_in[7];
    const float* bias = (const float*)d_in[8];
    float* y = (float*)d_out;

    k_in<<<NS, 128>>>(x, f3, f4, f5);
    dim3 g2(4, 32);     // N tiles x M tiles
    k_core<<<g2, 256>>>(core);
    k_out<<<NS, 128>>>(f0, f1, f2, bias, y);
}

// round 2
// speedup vs baseline: 1.0515x; 1.0515x over previous
#include <cuda_runtime.h>
#include <cstdint>

// Fused Tucker linear layer, fp32 with f32x2 packed FMA in the core GEMM.
//   z[n,lmn] = sum_{def} f3[d,l] f4[e,m] f5[f,nn] x[n,d,e,f]
//   u[n,ijk] = sum_{lmn} core[ijk,lmn] z[n,lmn]
//   y[n,abc] = sum_{ijk} f0[a,i] f1[b,j] f2[c,k] u[n,ijk] + bias
//
// Grid: 128 CTAs x 512 threads, 32 samples/CTA, single wave on 148 SMs.

#define THREADS 512
#define SPB 32      // samples per block
#define SB  8       // phase-1/3 sample sub-batch

// dynamic smem layout (floats):
//  zs   : [512][36]  z transposed [k][s], pad 36            -> 18432
//  usb  : [32][512]  u  (aliased as t1 in phase 1)          -> 16384
//  scr  : 16384      t2 (ph1) / core tile x2 (ph2) / s1 (ph3)
//  bss  : 4096       bias
//  fs   : 768        f0..f5
#define ZS_OFF   0
#define US_OFF   18432
#define SCR_OFF  (18432 + 16384)
#define BSS_OFF  (SCR_OFF + 16384)
#define FS_OFF   (BSS_OFF + 4096)
#define SMEM_FLOATS (FS_OFF + 768)
#define SMEM_BYTES (SMEM_FLOATS * 4)

__global__ __launch_bounds__(THREADS, 1) void tucker_fused(
    const float* __restrict__ x, const float* __restrict__ core,
    const float* __restrict__ f0, const float* __restrict__ f1,
    const float* __restrict__ f2, const float* __restrict__ f3,
    const float* __restrict__ f4, const float* __restrict__ f5,
    const float* __restrict__ bias, float* __restrict__ y)
{
    extern __shared__ float sm[];
    float* zs  = sm + ZS_OFF;
    float* usb = sm + US_OFF;
    float* scr = sm + SCR_OFF;
    float* bss = sm + BSS_OFF;
    float* fs  = sm + FS_OFF;

    const int tid = threadIdx.x;
    const int s0 = blockIdx.x * SPB;

    if (tid < 128) {
        fs[tid]       = f0[tid];
        fs[128 + tid] = f1[tid];
        fs[256 + tid] = f2[tid];
        fs[384 + tid] = f3[tid];
        fs[512 + tid] = f4[tid];
        fs[640 + tid] = f5[tid];
    }
    for (int i = tid; i < 4096; i += THREADS) bss[i] = bias[i];
    __syncthreads();

    // ---------------- PHASE 1: in-side contraction -> zs[k][s] ----------------
    {
        const float* f3s = fs + 384;
        const float* f4s = fs + 512;
        const float* f5s = fs + 640;
        float* t1 = usb;   // [SB][256][8]  (16384 floats)
        float* t2 = scr;   // [SB][16][8][8] (8192 floats)

        for (int sb = 0; sb < SPB; sb += SB) {
            // 1a: t1[sl][de][nn] = sum_f x[n, de*16+f] * f5[f][nn]
#pragma unroll
            for (int it = 0; it < (SB * 256) / THREADS; it++) {   // 4
                int r = it * THREADS + tid;       // sl*256 + de
                int sl = r >> 8, de = r & 255;
                const float4* xp = (const float4*)(x + ((size_t)(s0 + sb + sl) << 12) + de * 16);
                float4 x0 = xp[0], x1 = xp[1], x2 = xp[2], x3 = xp[3];
                float xv[16] = {x0.x, x0.y, x0.z, x0.w, x1.x, x1.y, x1.z, x1.w,
                                x2.x, x2.y, x2.z, x2.w, x3.x, x3.y, x3.z, x3.w};
                float v[8];
#pragma unroll
                for (int nn = 0; nn < 8; nn++) v[nn] = 0.f;
#pragma unroll
                for (int f = 0; f < 16; f++) {
                    float xf = xv[f];
#pragma unroll
                    for (int nn = 0; nn < 8; nn++) v[nn] += xf * f5s[f * 8 + nn];
                }
                float4* o = (float4*)(t1 + r * 8);
                o[0] = make_float4(v[0], v[1], v[2], v[3]);
                o[1] = make_float4(v[4], v[5], v[6], v[7]);
            }
            __syncthreads();
            // 1b: t2[sl][d][m][nn] = sum_e f4[e][m] * t1[sl][d*16+e][nn]
#pragma unroll 2
            for (int it = 0; it < (SB * 1024) / THREADS; it++) {  // 16
                int idx = it * THREADS + tid;
                int nn = idx & 7, m = (idx >> 3) & 7, d = (idx >> 6) & 15, sl = idx >> 10;
                const float* base = t1 + (((sl << 4) + d) << 7) + nn;
                float acc = 0.f;
#pragma unroll
                for (int e = 0; e < 16; e++) acc += f4s[e * 8 + m] * base[e * 8];
                t2[idx] = acc;
            }
            __syncthreads();
            // 1c: zs[k][sb+sl] = sum_d f3[d][l] * t2[sl][d][m][nn],  k=l*64+m*8+nn
#pragma unroll 2
            for (int it = 0; it < (SB * 512) / THREADS; it++) {   // 8
                int idx = it * THREADS + tid;
                int k = idx & 511, sl = idx >> 9;
                int mn = k & 63, l = k >> 6;
                const float* base = t2 + (sl << 10) + mn;
                float acc = 0.f;
#pragma unroll
                for (int d = 0; d < 16; d++) acc += f3s[d * 8 + l] * base[d << 6];
                zs[k * 36 + sb + sl] = acc;
            }
            __syncthreads();
        }
    }

    // ---------------- PHASE 2: U[32,512] = Z @ core^T (f32x2 packed FMA) -----
    {
        const int sg = tid >> 7;      // 0..3  -> s block of 8
        const int og = tid & 127;     // 0..127 -> o block of 4
        float* tile = scr;            // [2][8192]: tile[buf][o*16 + slot*4 + ...]

        unsigned long long acc2[4][4];   // [si2][oi], lanes = (s = sg*8+si2*2, s+1)
#pragma unroll
        for (int a = 0; a < 4; a++)
#pragma unroll
            for (int b = 0; b < 4; b++) acc2[a][b] = 0ull;

        // prologue: load k-tile 0 into buf 0 (core row-major [o][k], kept k-major)
#pragma unroll
        for (int i = 0; i < 4; i++) {
            int g = i * THREADS + tid;
            int o = g >> 2, kq = g & 3;
            float4 v = ((const float4*)core)[o * 128 + kq];
            int slot = kq ^ ((o >> 2) & 3);
            *(float4*)&tile[o * 16 + slot * 4] = v;
        }
        __syncthreads();

#pragma unroll 1
        for (int kt = 0; kt < 32; kt++) {
            const int cur = kt & 1;
            float4 pf[4];
            if (kt < 31) {
#pragma unroll
                for (int i = 0; i < 4; i++) {
                    int g = i * THREADS + tid;
                    int o = g >> 2, kq = g & 3;
                    pf[i] = ((const float4*)core)[o * 128 + (kt + 1) * 4 + kq];
                }
            }
            const float* tb = tile + cur * 8192;
#pragma unroll
            for (int kq = 0; kq < 4; kq++) {
                float bb[4][4];
#pragma unroll
                for (int oi = 0; oi < 4; oi++) {
                    int o = og * 4 + oi;
                    int slot = kq ^ (og & 3);
                    *(float4*)bb[oi] = *(const float4*)&tb[o * 16 + slot * 4];
                }
#pragma unroll
                for (int k = 0; k < 4; k++) {
                    const float* ap = zs + (kt * 16 + kq * 4 + k) * 36 + sg * 8;
                    ulonglong2 A0 = *(const ulonglong2*)ap;       // (s0,s1),(s2,s3)
                    ulonglong2 A1 = *(const ulonglong2*)(ap + 4); // (s4,s5),(s6,s7)
                    unsigned long long av[4] = {A0.x, A0.y, A1.x, A1.y};
#pragma unroll
                    for (int oi = 0; oi < 4; oi++) {
                        unsigned long long bd;
                        asm("mov.b64 %0, {%1, %1};" : "=l"(bd) : "f"(bb[oi][k]));
#pragma unroll
                        for (int si2 = 0; si2 < 4; si2++) {
                            asm("fma.rn.f32x2 %0, %1, %2, %0;"
                                : "+l"(acc2[si2][oi]) : "l"(av[si2]), "l"(bd));
                        }
                    }
                }
            }
            if (kt < 31) {
#pragma unroll
                for (int i = 0; i < 4; i++) {
                    int g = i * THREADS + tid;
                    int o = g >> 2, kq = g & 3;
                    int slot = kq ^ ((o >> 2) & 3);
                    *(float4*)&tile[(1 - cur) * 8192 + o * 16 + slot * 4] = pf[i];
                }
            }
            __syncthreads();
        }

        // unpack + store U to usb[s][512]
#pragma unroll
        for (int si2 = 0; si2 < 4; si2++) {
            float lo[4], hi[4];
#pragma unroll
            for (int oi = 0; oi < 4; oi++) {
                asm("mov.b64 {%0, %1}, %2;" : "=f"(lo[oi]), "=f"(hi[oi]) : "l"(acc2[si2][oi]));
            }
            int s = sg * 8 + si2 * 2;
            *(float4*)&usb[s * 512 + og * 4]       = make_float4(lo[0], lo[1], lo[2], lo[3]);
            *(float4*)&usb[(s + 1) * 512 + og * 4] = make_float4(hi[0], hi[1], hi[2], hi[3]);
        }
        __syncthreads();
    }

    // ---------------- PHASE 3: out-side expansion + bias -> y -----------------
    {
        const float* f0s = fs;
        const float* f1s = fs + 128;
        const float* f2s = fs + 256;
        float* s1 = scr;   // [SB][16][8][8] = 8192 floats

        for (int sb = 0; sb < SPB; sb += SB) {
            // s1[sl][a][j][k] = sum_i f0[a][i] * u[s][i*64 + j*8 + k]
#pragma unroll 2
            for (int it = 0; it < (SB * 1024) / THREADS; it++) {  // 16
                int idx = it * THREADS + tid;
                int jk = idx & 63, a = (idx >> 6) & 15, sl = idx >> 10;
                const float* ub = usb + (sb + sl) * 512 + jk;
                float acc = 0.f;
#pragma unroll
                for (int i = 0; i < 8; i++) acc += f0s[a * 8 + i] * ub[i * 64];
                s1[idx] = acc;
            }
            __syncthreads();
            // y[s][a*256 + b*16 + c] = sum_k f2[c][k] * (sum_j f1[b][j]*s1[sl][a][j][k]) + bias
#pragma unroll
            for (int it = 0; it < (SB * 256) / THREADS; it++) {   // 4
                int r = it * THREADS + tid;       // sl*256 + a*16 + b
                int b = r & 15, a = (r >> 4) & 15, sl = r >> 8;
                const float* sp = s1 + ((sl * 16 + a) << 6);
                float w[8];
#pragma unroll
                for (int k = 0; k < 8; k++) {
                    float acc = 0.f;
#pragma unroll
                    for (int j = 0; j < 8; j++) acc += f1s[b * 8 + j] * sp[j * 8 + k];
                    w[k] = acc;
                }
                float* yo = y + ((size_t)(s0 + sb + sl) << 12) + a * 256 + b * 16;
                const float* bp = bss + a * 256 + b * 16;
#pragma unroll
                for (int c4 = 0; c4 < 4; c4++) {
                    float out[4];
#pragma unroll
                    for (int ci = 0; ci < 4; ci++) {
                        int c = c4 * 4 + ci;
                        float acc = bp[c];
#pragma unroll
                        for (int k = 0; k < 8; k++) acc += f2s[c * 8 + k] * w[k];
                        out[ci] = acc;
                    }
                    *(float4*)(yo + c4 * 4) = make_float4(out[0], out[1], out[2], out[3]);
                }
            }
            __syncthreads();
        }
    }
}

extern "C" void kernel_launch(void* const* d_in, const int* in_sizes, int n_in,
                              void* d_out, int out_size) {
    const float* x    = (const float*)d_in[0];
    const float* core = (const float*)d_in[1];
    const float* f0   = (const float*)d_in[2];
    const float* f1   = (const float*)d_in[3];
    const float* f2   = (const float*)d_in[4];
    const float* f3   = (const float*)d_in[5];
    const float* f4   = (const float*)d_in[6];
    const float* f5   = (const float*)d_in[7];
    const float* bias = (const float*)d_in[8];
    float* y = (float*)d_out;

    cudaFuncSetAttribute(tucker_fused, cudaFuncAttributeMaxDynamicSharedMemorySize, SMEM_BYTES);
    tucker_fused<<<128, THREADS, SMEM_BYTES>>>(x, core, f0, f1, f2, f3, f4, f5, bias, y);
}